// round 15
// baseline (speedup 1.0000x reference)
#include <cuda_runtime.h>
#include <cuda_fp16.h>
#include <cstdint>
#include <math.h>

#define SEQ_    2048
#define DIN_    2048
#define NH_     32
#define NKV_    8
#define HD_     64
#define DQKV_   3072            // Q(2048) | K(512) | V(512) fused columns
#define DOUT_   2048
#define GK_     2048            // GEMM K (both GEMMs have K=2048)

// ---------------------------------------------------------------------------
// Scratch (__device__ globals; allocation-free rule)
// ---------------------------------------------------------------------------
__device__ __half g_xh[SEQ_ * DIN_];       // x in fp16
__device__ __half g_wth[DQKV_ * DIN_];     // W_qkv^T [3072][2048] fp16
__device__ __half g_woth[DIN_ * DOUT_];    // Wo^T    [2048][2048] fp16
__device__ float  g_QKV[SEQ_ * DQKV_];     // fp32 GEMM out: Q | K | V
__device__ __half g_Kh[SEQ_ * 512];        // normed+roped K, fp16 [seq][kvh*64]
__device__ __half g_Vth[NKV_ * HD_ * SEQ_];// V transposed fp16 [kvh][dim][seq]
__device__ __half g_Ah[SEQ_ * DOUT_];      // attention out fp16

// ---------------------------------------------------------------------------
// Helpers (baseline PTX only)
// ---------------------------------------------------------------------------
__device__ __forceinline__ uint32_t smem_u32(const void* p) {
    uint32_t a;
    asm("{ .reg .u64 t; cvta.to.shared.u64 t, %1; cvt.u32.u64 %0, t; }" : "=r"(a) : "l"(p));
    return a;
}
__device__ __forceinline__ void cpasync16(uint32_t dst, const void* src) {
    asm volatile("cp.async.cg.shared.global [%0], [%1], 16;" :: "r"(dst), "l"(src));
}
#define CP_COMMIT()  asm volatile("cp.async.commit_group;" ::: "memory")
#define CP_WAIT(n)   asm volatile("cp.async.wait_group %0;" :: "n"(n) : "memory")

// fp16 mma: D(f32) += A(f16) * B(f16), m16n8k16
__device__ __forceinline__ void mma_f16(float* d, const uint32_t* a, const uint32_t* b) {
    asm volatile(
        "mma.sync.aligned.m16n8k16.row.col.f32.f16.f16.f32 "
        "{%0,%1,%2,%3}, {%4,%5,%6,%7}, {%8,%9}, {%0,%1,%2,%3};"
        : "+f"(d[0]), "+f"(d[1]), "+f"(d[2]), "+f"(d[3])
        : "r"(a[0]), "r"(a[1]), "r"(a[2]), "r"(a[3]), "r"(b[0]), "r"(b[1]));
}
// ldmatrix x4: 4 8x8 fp16 matrices; lane L supplies row address for matrix L/8
__device__ __forceinline__ void ldm_x4(uint32_t* r, uint32_t addr) {
    asm volatile("ldmatrix.sync.aligned.m8n8.x4.shared.b16 {%0,%1,%2,%3}, [%4];"
        : "=r"(r[0]), "=r"(r[1]), "=r"(r[2]), "=r"(r[3]) : "r"(addr));
}
__device__ __forceinline__ uint32_t packh2(float x, float y) {
    __half2 h = __floats2half2_rn(x, y);
    return *(uint32_t*)&h;
}

// ---------------------------------------------------------------------------
// Prep kernels
// ---------------------------------------------------------------------------
__global__ void cvt_h(const float* __restrict__ src, __half* __restrict__ dst, int n2) {
    int i = blockIdx.x * blockDim.x + threadIdx.x;
    if (i >= n2) return;
    float2 v = ((const float2*)src)[i];
    ((uint32_t*)dst)[i] = packh2(v.x, v.y);
}

__device__ __forceinline__ void tpose_body(const float* __restrict__ W, int ncols,
                                           __half* __restrict__ out, int row_off,
                                           int bx, int by) {
    __shared__ float t[32][33];
    int tx = threadIdx.x, ty = threadIdx.y;
    int x = bx * 32 + tx;
    int y = by * 32 + ty;
#pragma unroll
    for (int i = 0; i < 32; i += 8)
        t[ty + i][tx] = W[(size_t)(y + i) * ncols + x];
    __syncthreads();
    int n = bx * 32 + ty;
    int k = by * 32 + tx;
#pragma unroll
    for (int i = 0; i < 32; i += 8)
        out[(size_t)(row_off + n + i) * GK_ + k] = __float2half_rn(t[tx][ty + i]);
}

__global__ void tposer(const float* __restrict__ W, int ncols,
                       __half* __restrict__ out, int row_off) {
    tpose_body(W, ncols, out, row_off, blockIdx.x, blockIdx.y);
}

__global__ void tposer3(const float* __restrict__ wq, const float* __restrict__ wk,
                        const float* __restrict__ wv, __half* __restrict__ out) {
    int z = blockIdx.z;
    if (z == 0) {
        tpose_body(wq, 2048, out, 0, blockIdx.x, blockIdx.y);
    } else if (z == 1) {
        if (blockIdx.x < 16) tpose_body(wk, 512, out, 2048, blockIdx.x, blockIdx.y);
    } else {
        if (blockIdx.x < 16) tpose_body(wv, 512, out, 2560, blockIdx.x, blockIdx.y);
    }
}

__global__ void vtpose() {
    __shared__ float t[32][33];
    int tx = threadIdx.x, ty = threadIdx.y;
    int kvh = blockIdx.z;
    int dim0 = blockIdx.x * 32;
    int seq0 = blockIdx.y * 32;
#pragma unroll
    for (int i = 0; i < 32; i += 8)
        t[ty + i][tx] = g_QKV[(size_t)(seq0 + ty + i) * DQKV_ + 2560 + kvh * HD_ + dim0 + tx];
    __syncthreads();
#pragma unroll
    for (int i = 0; i < 32; i += 8)
        g_Vth[(size_t)kvh * HD_ * SEQ_ + (size_t)(dim0 + ty + i) * SEQ_ + seq0 + tx] =
            __float2half_rn(t[tx][ty + i]);
}

// ---------------------------------------------------------------------------
// Fused RMSNorm + RoPE. Q pass: fp32 in place. K pass: fp16 out to g_Kh.
// ---------------------------------------------------------------------------
__global__ void norm_rope(float* __restrict__ X, const float* __restrict__ w,
                          const float* __restrict__ cosp, const float* __restrict__ sinp,
                          int nheads, int rowdim, __half* __restrict__ hout) {
    int gwarp = (blockIdx.x * blockDim.x + threadIdx.x) >> 5;
    int lane = threadIdx.x & 31;
    int s = gwarp / nheads;
    int h = gwarp % nheads;
    if (s >= SEQ_) return;

    float* p = X + (size_t)s * rowdim + h * HD_;
    float x0 = p[lane];
    float x1 = p[lane + 32];

    float ss = x0 * x0 + x1 * x1;
#pragma unroll
    for (int off = 16; off; off >>= 1) ss += __shfl_xor_sync(0xFFFFFFFFu, ss, off);
    float r = rsqrtf(ss * (1.f / 64.f) + 1e-6f);

    x0 = x0 * r * w[lane];
    x1 = x1 * r * w[lane + 32];

    float c0 = cosp[s * HD_ + lane],      s0 = sinp[s * HD_ + lane];
    float c1 = cosp[s * HD_ + lane + 32], s1 = sinp[s * HD_ + lane + 32];

    float y0 = x0 * c0 - x1 * s0;
    float y1 = x1 * c1 + x0 * s1;
    if (hout) {
        __half* q = hout + (size_t)s * 512 + h * HD_;
        q[lane]      = __float2half_rn(y0);
        q[lane + 32] = __float2half_rn(y1);
    } else {
        p[lane]      = y0;
        p[lane + 32] = y1;
    }
}

// ---------------------------------------------------------------------------
// fp16 mma.sync GEMM with ldmatrix fragments.
// CTA tile 64x128, BK=32, 4 warps (2x2, warp tile 32x64), 128 threads,
// 3-stage cp.async, 4 CTAs/SM. Row stride 20 words -> conflict-free ldmatrix.
// ---------------------------------------------------------------------------
#define NCHG_   (GK_ / 32)      // 64
#define GW_     20              // words per smem row (32 halves + pad)
#define AROWS_  64
#define SROWS_  192             // 64 A rows + 128 B rows
#define SSTG_W  (SROWS_ * GW_)  // 3840 words per stage
#define GNSTG_  3

__global__ __launch_bounds__(128, 4) void gemm_f16(
    const __half* __restrict__ A, const __half* __restrict__ Bt,
    float* __restrict__ C, int ldc)
{
    extern __shared__ uint32_t smw[];
    const int tid = threadIdx.x;
    const int w = tid >> 5, lane = tid & 31;
    const int bm = blockIdx.y * 64, bn = blockIdx.x * 128;
    const int warp_m = (w & 1) * 32, warp_n = (w >> 1) * 64;
    const int tr = lane >> 2, tc = lane & 3;

    float acc[2][8][4];
#pragma unroll
    for (int i = 0; i < 2; i++)
#pragma unroll
        for (int j = 0; j < 8; j++)
#pragma unroll
            for (int r = 0; r < 4; r++) acc[i][j][r] = 0.f;

    const __half* Ag = A + (size_t)bm * GK_;
    const __half* Bg = Bt + (size_t)bn * GK_;
    const int lrow = tid >> 2;
    const int lq = tid & 3;
    uint32_t sbase = smem_u32(smw);

    // ldmatrix lane-address offsets (bytes, within stage)
    // A x4: m0/m1 = rows +0/+8 (k 0-7), m2/m3 = rows +0/+8 (k 8-15)
    const int aLrow = ((lane >> 3) & 1) * 8 + (lane & 7);
    const int aLcol = ((lane >> 4) & 1) * 4;
    uint32_t aoff[2];
#pragma unroll
    for (int mt = 0; mt < 2; mt++)
        aoff[mt] = (uint32_t)((warp_m + mt * 16 + aLrow) * GW_ + aLcol) * 4;
    // B x4: m0/m1 = n rows +0..7 (k 0-7 / 8-15), m2/m3 = n rows +8..15
    const int bLrow = ((lane >> 4) & 1) * 8 + (lane & 7);
    const int bLcol = ((lane >> 3) & 1) * 4;
    uint32_t boff[4];
#pragma unroll
    for (int p = 0; p < 4; p++)
        boff[p] = (uint32_t)(AROWS_ * GW_ + (warp_n + p * 16 + bLrow) * GW_ + bLcol) * 4;

    auto issue = [&](int c) {
        uint32_t sA = sbase + (uint32_t)(c % GNSTG_) * SSTG_W * 4;
        uint32_t sB = sA + AROWS_ * GW_ * 4;
        const int k0 = c * 32;
#pragma unroll
        for (int i = 0; i < 2; i++) {
            int row = lrow + i * 32;
            cpasync16(sA + (uint32_t)(row * GW_ + lq * 4) * 4,
                      Ag + (size_t)row * GK_ + k0 + lq * 8);
        }
#pragma unroll
        for (int i = 0; i < 4; i++) {
            int row = lrow + i * 32;
            cpasync16(sB + (uint32_t)(row * GW_ + lq * 4) * 4,
                      Bg + (size_t)row * GK_ + k0 + lq * 8);
        }
        CP_COMMIT();
    };

    issue(0); issue(1);

    for (int c = 0; c < NCHG_; c++) {
        if (c + 1 < NCHG_) CP_WAIT(1); else CP_WAIT(0);
        __syncthreads();
        if (c + 2 < NCHG_) issue(c + 2);   // stage (c+2)%3 == (c-1)%3, freed by barrier

        const uint32_t stg = sbase + (uint32_t)(c % GNSTG_) * SSTG_W * 4;

#pragma unroll
        for (int kk = 0; kk < 2; kk++) {
            const uint32_t kbo = (uint32_t)kk * 32;   // k16 step = 8 words = 32 B
            uint32_t a[2][4], b[8][2];
#pragma unroll
            for (int mt = 0; mt < 2; mt++)
                ldm_x4(a[mt], stg + aoff[mt] + kbo);
#pragma unroll
            for (int p = 0; p < 4; p++) {
                uint32_t r[4];
                ldm_x4(r, stg + boff[p] + kbo);
                b[2 * p][0] = r[0]; b[2 * p][1] = r[1];
                b[2 * p + 1][0] = r[2]; b[2 * p + 1][1] = r[3];
            }
#pragma unroll
            for (int mt = 0; mt < 2; mt++)
#pragma unroll
                for (int nt = 0; nt < 8; nt++)
                    mma_f16(acc[mt][nt], a[mt], b[nt]);
        }
    }

#pragma unroll
    for (int mt = 0; mt < 2; mt++)
#pragma unroll
        for (int nt = 0; nt < 8; nt++) {
            int row = bm + warp_m + mt * 16 + tr;
            int col = bn + warp_n + nt * 8 + 2 * tc;
            *(float2*)(C + (size_t)row * ldc + col) =
                make_float2(acc[mt][nt][0], acc[mt][nt][1]);
            *(float2*)(C + (size_t)(row + 8) * ldc + col) =
                make_float2(acc[mt][nt][2], acc[mt][nt][3]);
        }
}

// ---------------------------------------------------------------------------
// fp16 tensor-core causal GQA flash attention, ldmatrix fragment loads.
// ---------------------------------------------------------------------------
#define QS_ST   68
#define KW_     36
#define VW_     20
#define KS_OFFW (128 * QS_ST)
#define VS_OFFW (KS_OFFW + 2 * 32 * KW_)
#define FA_SMW  (VS_OFFW + 2 * 64 * VW_)    // 13568 words = 54272 B

__global__ __launch_bounds__(256, 2) void flash_f16() {
    extern __shared__ uint32_t smw[];
    float* Qs = (float*)smw;
    const int tid = threadIdx.x;
    const int w = tid >> 5, lane = tid & 31;
    const int tr = lane >> 2, tc = lane & 3;
    const int h = blockIdx.y;
    const int q0 = blockIdx.x * 128;
    const int kvh = h >> 2;
    const uint32_t sb = smem_u32(smw);

    const __half* Kg = g_Kh + kvh * HD_;
    const __half* Vg = g_Vth + (size_t)kvh * HD_ * SEQ_;

    // ldmatrix B-frag lane offsets (bytes within tile)
    const int bLrow = ((lane >> 4) & 1) * 8 + (lane & 7);
    const int bLcol = ((lane >> 3) & 1) * 4;
    uint32_t koff[2], voff[4];
#pragma unroll
    for (int p = 0; p < 2; p++)
        koff[p] = (uint32_t)((p * 16 + bLrow) * KW_ + bLcol) * 4;
#pragma unroll
    for (int p = 0; p < 4; p++)
        voff[p] = (uint32_t)((p * 16 + bLrow) * VW_ + bLcol) * 4;

    {
        int kr = tid >> 3, kq = tid & 7;
        cpasync16(sb + (KS_OFFW + kr * KW_ + kq * 4) * 4,
                  Kg + (size_t)kr * 512 + kq * 8);
        int vr = tid >> 2, vq = tid & 3;
        cpasync16(sb + (VS_OFFW + vr * VW_ + vq * 4) * 4,
                  Vg + (size_t)vr * SEQ_ + vq * 8);
        CP_COMMIT();
    }

    {
        const float* Qgp = g_QKV + (size_t)q0 * DQKV_ + h * HD_;
#pragma unroll
        for (int i = 0; i < 8; i++) {
            int idx = tid + i * 256;
            int row = idx >> 4, c4 = idx & 15;
            *(float4*)&Qs[row * QS_ST + c4 * 4] =
                *(const float4*)(Qgp + (size_t)row * DQKV_ + c4 * 4);
        }
    }
    __syncthreads();

    uint32_t q[4][4];
    {
        const float scale = 0.125f;
        const float* q0p = Qs + (w * 16 + tr) * QS_ST;
        const float* q1p = q0p + 8 * QS_ST;
#pragma unroll
        for (int kk = 0; kk < 4; kk++) {
            int c = 16 * kk + 2 * tc;
            q[kk][0] = packh2(q0p[c] * scale, q0p[c + 1] * scale);
            q[kk][1] = packh2(q1p[c] * scale, q1p[c + 1] * scale);
            q[kk][2] = packh2(q0p[c + 8] * scale, q0p[c + 9] * scale);
            q[kk][3] = packh2(q1p[c + 8] * scale, q1p[c + 9] * scale);
        }
    }

    float o[8][4];
#pragma unroll
    for (int nf = 0; nf < 8; nf++)
#pragma unroll
        for (int r = 0; r < 4; r++) o[nf][r] = 0.f;
    float m0 = -1e30f, m1 = -1e30f, l0 = 0.f, l1 = 0.f;

    const int ntiles = (q0 + 128) / 32;

    for (int t = 0; t < ntiles; t++) {
        const int k0 = t * 32;
        if (t + 1 < ntiles) {
            const int kn = (t + 1) * 32;
            const int buf = (t + 1) & 1;
            int kr = tid >> 3, kq = tid & 7;
            cpasync16(sb + (KS_OFFW + (buf * 32 + kr) * KW_ + kq * 4) * 4,
                      Kg + (size_t)(kn + kr) * 512 + kq * 8);
            int vr = tid >> 2, vq = tid & 3;
            cpasync16(sb + (VS_OFFW + (buf * 64 + vr) * VW_ + vq * 4) * 4,
                      Vg + (size_t)vr * SEQ_ + kn + vq * 8);
            CP_COMMIT();
            CP_WAIT(1);
        } else {
            CP_WAIT(0);
        }
        __syncthreads();

        if (k0 <= q0 + w * 16 + 15) {
            const uint32_t ktaddr = sb + (uint32_t)(KS_OFFW + (t & 1) * 32 * KW_) * 4;
            const uint32_t vtaddr = sb + (uint32_t)(VS_OFFW + (t & 1) * 64 * VW_) * 4;

            // ---- scores: S[16][32] = Q @ K^T, ldmatrix K frags ----
            float s[4][4];
#pragma unroll
            for (int nf = 0; nf < 4; nf++)
                s[nf][0] = s[nf][1] = s[nf][2] = s[nf][3] = 0.f;
#pragma unroll
            for (int kk = 0; kk < 4; kk++) {
                uint32_t kb[4][2];
#pragma unroll
                for (int p = 0; p < 2; p++) {
                    uint32_t r[4];
                    ldm_x4(r, ktaddr + koff[p] + (uint32_t)kk * 32);
                    kb[2 * p][0] = r[0]; kb[2 * p][1] = r[1];
                    kb[2 * p + 1][0] = r[2]; kb[2 * p + 1][1] = r[3];
                }
#pragma unroll
                for (int nf = 0; nf < 4; nf++)
                    mma_f16(s[nf], q[kk], kb[nf]);
            }

            if (k0 + 31 > q0 + w * 16) {
                const int r0 = q0 + w * 16 + tr, r1 = r0 + 8;
                const int cb = k0 + 2 * tc;
#pragma unroll
                for (int nf = 0; nf < 4; nf++) {
                    int c0 = cb + nf * 8, c1 = c0 + 1;
                    if (c0 > r0) s[nf][0] = -1e30f;
                    if (c1 > r0) s[nf][1] = -1e30f;
                    if (c0 > r1) s[nf][2] = -1e30f;
                    if (c1 > r1) s[nf][3] = -1e30f;
                }
            }

            float t0 = fmaxf(fmaxf(s[0][0], s[0][1]), fmaxf(s[1][0], s[1][1]));
            t0 = fmaxf(t0, fmaxf(fmaxf(s[2][0], s[2][1]), fmaxf(s[3][0], s[3][1])));
            float t1 = fmaxf(fmaxf(s[0][2], s[0][3]), fmaxf(s[1][2], s[1][3]));
            t1 = fmaxf(t1, fmaxf(fmaxf(s[2][2], s[2][3]), fmaxf(s[3][2], s[3][3])));
            t0 = fmaxf(t0, __shfl_xor_sync(0xFFFFFFFFu, t0, 1));
            t0 = fmaxf(t0, __shfl_xor_sync(0xFFFFFFFFu, t0, 2));
            t1 = fmaxf(t1, __shfl_xor_sync(0xFFFFFFFFu, t1, 1));
            t1 = fmaxf(t1, __shfl_xor_sync(0xFFFFFFFFu, t1, 2));
            const float mt0 = fmaxf(m0, t0), mt1 = fmaxf(m1, t1);
            const float corr0 = __expf(m0 - mt0), corr1 = __expf(m1 - mt1);
            m0 = mt0; m1 = mt1;

            float pv[4][4];
            float sum0 = 0.f, sum1 = 0.f;
#pragma unroll
            for (int nf = 0; nf < 4; nf++) {
                pv[nf][0] = __expf(s[nf][0] - mt0);
                pv[nf][1] = __expf(s[nf][1] - mt0);
                pv[nf][2] = __expf(s[nf][2] - mt1);
                pv[nf][3] = __expf(s[nf][3] - mt1);
                sum0 += pv[nf][0] + pv[nf][1];
                sum1 += pv[nf][2] + pv[nf][3];
            }
            sum0 += __shfl_xor_sync(0xFFFFFFFFu, sum0, 1);
            sum0 += __shfl_xor_sync(0xFFFFFFFFu, sum0, 2);
            sum1 += __shfl_xor_sync(0xFFFFFFFFu, sum1, 1);
            sum1 += __shfl_xor_sync(0xFFFFFFFFu, sum1, 2);
            l0 = l0 * corr0 + sum0;
            l1 = l1 * corr1 + sum1;

#pragma unroll
            for (int nf = 0; nf < 8; nf++) {
                o[nf][0] *= corr0; o[nf][1] *= corr0;
                o[nf][2] *= corr1; o[nf][3] *= corr1;
            }

            // ---- O += P @ V, P reg->reg, ldmatrix V frags ----
#pragma unroll
            for (int kkp = 0; kkp < 2; kkp++) {
                uint32_t a[4] = {
                    packh2(pv[2 * kkp][0],     pv[2 * kkp][1]),
                    packh2(pv[2 * kkp][2],     pv[2 * kkp][3]),
                    packh2(pv[2 * kkp + 1][0], pv[2 * kkp + 1][1]),
                    packh2(pv[2 * kkp + 1][2], pv[2 * kkp + 1][3])
                };
                uint32_t vb[8][2];
#pragma unroll
                for (int p = 0; p < 4; p++) {
                    uint32_t r[4];
                    ldm_x4(r, vtaddr + voff[p] + (uint32_t)kkp * 32);
                    vb[2 * p][0] = r[0]; vb[2 * p][1] = r[1];
                    vb[2 * p + 1][0] = r[2]; vb[2 * p + 1][1] = r[3];
                }
#pragma unroll
                for (int nt = 0; nt < 8; nt++)
                    mma_f16(o[nt], a, vb[nt]);
            }
        }
        __syncthreads();
    }

    const float inv0 = 1.f / l0, inv1 = 1.f / l1;
    const int r0 = q0 + w * 16 + tr;
    uint32_t* Og = (uint32_t*)(g_Ah + (size_t)r0 * DOUT_ + h * HD_ + 2 * tc);
    uint32_t* Og8 = (uint32_t*)(g_Ah + (size_t)(r0 + 8) * DOUT_ + h * HD_ + 2 * tc);
#pragma unroll
    for (int nf = 0; nf < 8; nf++) {
        Og[nf * 4]  = packh2(o[nf][0] * inv0, o[nf][1] * inv0);
        Og8[nf * 4] = packh2(o[nf][2] * inv1, o[nf][3] * inv1);
    }
}

// ---------------------------------------------------------------------------
extern "C" void kernel_launch(void* const* d_in, const int* in_sizes, int n_in,
                              void* d_out, int out_size) {
    const float* x    = (const float*)d_in[0];
    const float* cosp = (const float*)d_in[1];
    const float* sinp = (const float*)d_in[2];
    const float* wq   = (const float*)d_in[3];
    const float* wk   = (const float*)d_in[4];
    const float* wv   = (const float*)d_in[5];
    const float* wo   = (const float*)d_in[6];
    const float* qw   = (const float*)d_in[7];
    const float* kw   = (const float*)d_in[8];
    float* out = (float*)d_out;

    float *QKV;
    __half *xh, *wth, *woth, *Kh, *Ah;
    cudaGetSymbolAddress((void**)&xh,   g_xh);
    cudaGetSymbolAddress((void**)&wth,  g_wth);
    cudaGetSymbolAddress((void**)&woth, g_woth);
    cudaGetSymbolAddress((void**)&QKV,  g_QKV);
    cudaGetSymbolAddress((void**)&Kh,   g_Kh);
    cudaGetSymbolAddress((void**)&Ah,   g_Ah);

    const int gsmem = GNSTG_ * SSTG_W * 4;    // 46080 B (3 stages)
    cudaFuncSetAttribute(gemm_f16, cudaFuncAttributeMaxDynamicSharedMemorySize, gsmem);
    const int fsmem = FA_SMW * 4;             // 54272 B
    cudaFuncSetAttribute(flash_f16, cudaFuncAttributeMaxDynamicSharedMemorySize, fsmem);

    // Prep: x -> fp16; weights transpose -> fp16
    cvt_h<<<(SEQ_ * DIN_ / 2 + 255) / 256, 256>>>(x, xh, SEQ_ * DIN_ / 2);
    tposer3<<<dim3(64, DIN_ / 32, 3), dim3(32, 8)>>>(wq, wk, wv, wth);
    tposer<<<dim3(2048 / 32, DOUT_ / 32), dim3(32, 8)>>>(wo, 2048, woth, 0);

    // Fused QKV projection (fp16 tensor cores, fp32 out), 64x128 tiles
    gemm_f16<<<dim3(DQKV_ / 128, SEQ_ / 64), 128, gsmem>>>(xh, wth, QKV, DQKV_);

    // RMSNorm + RoPE: Q in place fp32; K -> fp16 g_Kh. V -> transposed fp16.
    norm_rope<<<(SEQ_ * NH_ * 32) / 256, 256>>>(QKV, qw, cosp, sinp, NH_, DQKV_, (half*)0);
    norm_rope<<<(SEQ_ * NKV_ * 32) / 256, 256>>>(QKV + 2048, kw, cosp, sinp, NKV_, DQKV_, Kh);
    vtpose<<<dim3(HD_ / 32, SEQ_ / 32, NKV_), dim3(32, 8)>>>();

    // Tensor-core causal GQA attention (fp16), writes fp16 g_Ah
    flash_f16<<<dim3(SEQ_ / 128, NH_), 256, fsmem>>>();

    // Output projection (fp16 tensor cores, fp32 out), 64x128 tiles
    gemm_f16<<<dim3(DIN_ / 128, SEQ_ / 64), 128, gsmem>>>(Ah, woth, out, DIN_);
}

// round 16
// speedup vs baseline: 1.2601x; 1.2601x over previous
#include <cuda_runtime.h>
#include <cuda_fp16.h>
#include <cstdint>
#include <math.h>

#define SEQ_    2048
#define DIN_    2048
#define NH_     32
#define NKV_    8
#define HD_     64
#define DQKV_   3072            // Q(2048) | K(512) | V(512) fused columns
#define DOUT_   2048
#define GK_     2048            // GEMM K (both GEMMs have K=2048)

// ---------------------------------------------------------------------------
// Scratch (__device__ globals; allocation-free rule)
// ---------------------------------------------------------------------------
__device__ __half g_xh[SEQ_ * DIN_];       // x in fp16
__device__ __half g_wth[DQKV_ * DIN_];     // W_qkv^T [3072][2048] fp16
__device__ __half g_woth[DIN_ * DOUT_];    // Wo^T    [2048][2048] fp16
__device__ float  g_QKV[SEQ_ * DQKV_];     // fp32 GEMM out: Q | K | V
__device__ __half g_Kh[SEQ_ * 512];        // normed+roped K, fp16 [seq][kvh*64]
__device__ __half g_Vth[NKV_ * HD_ * SEQ_];// V transposed fp16 [kvh][dim][seq]
__device__ __half g_Ah[SEQ_ * DOUT_];      // attention out fp16

// ---------------------------------------------------------------------------
// Helpers (baseline PTX only)
// ---------------------------------------------------------------------------
__device__ __forceinline__ uint32_t smem_u32(const void* p) {
    uint32_t a;
    asm("{ .reg .u64 t; cvta.to.shared.u64 t, %1; cvt.u32.u64 %0, t; }" : "=r"(a) : "l"(p));
    return a;
}
__device__ __forceinline__ void cpasync16(uint32_t dst, const void* src) {
    asm volatile("cp.async.cg.shared.global [%0], [%1], 16;" :: "r"(dst), "l"(src));
}
#define CP_COMMIT()  asm volatile("cp.async.commit_group;" ::: "memory")
#define CP_WAIT(n)   asm volatile("cp.async.wait_group %0;" :: "n"(n) : "memory")

// fp16 mma: D(f32) += A(f16) * B(f16), m16n8k16
__device__ __forceinline__ void mma_f16(float* d, const uint32_t* a, const uint32_t* b) {
    asm volatile(
        "mma.sync.aligned.m16n8k16.row.col.f32.f16.f16.f32 "
        "{%0,%1,%2,%3}, {%4,%5,%6,%7}, {%8,%9}, {%0,%1,%2,%3};"
        : "+f"(d[0]), "+f"(d[1]), "+f"(d[2]), "+f"(d[3])
        : "r"(a[0]), "r"(a[1]), "r"(a[2]), "r"(a[3]), "r"(b[0]), "r"(b[1]));
}
__device__ __forceinline__ uint32_t packh2(float x, float y) {
    __half2 h = __floats2half2_rn(x, y);
    return *(uint32_t*)&h;
}

// ---------------------------------------------------------------------------
// Prep kernels
// ---------------------------------------------------------------------------
__global__ void cvt_h(const float* __restrict__ src, __half* __restrict__ dst, int n2) {
    int i = blockIdx.x * blockDim.x + threadIdx.x;
    if (i >= n2) return;
    float2 v = ((const float2*)src)[i];
    ((uint32_t*)dst)[i] = packh2(v.x, v.y);
}

__device__ __forceinline__ void tpose_body(const float* __restrict__ W, int ncols,
                                           __half* __restrict__ out, int row_off,
                                           int bx, int by) {
    __shared__ float t[32][33];
    int tx = threadIdx.x, ty = threadIdx.y;
    int x = bx * 32 + tx;
    int y = by * 32 + ty;
#pragma unroll
    for (int i = 0; i < 32; i += 8)
        t[ty + i][tx] = W[(size_t)(y + i) * ncols + x];
    __syncthreads();
    int n = bx * 32 + ty;
    int k = by * 32 + tx;
#pragma unroll
    for (int i = 0; i < 32; i += 8)
        out[(size_t)(row_off + n + i) * GK_ + k] = __float2half_rn(t[tx][ty + i]);
}

__global__ void tposer(const float* __restrict__ W, int ncols,
                       __half* __restrict__ out, int row_off) {
    tpose_body(W, ncols, out, row_off, blockIdx.x, blockIdx.y);
}

__global__ void tposer3(const float* __restrict__ wq, const float* __restrict__ wk,
                        const float* __restrict__ wv, __half* __restrict__ out) {
    int z = blockIdx.z;
    if (z == 0) {
        tpose_body(wq, 2048, out, 0, blockIdx.x, blockIdx.y);
    } else if (z == 1) {
        if (blockIdx.x < 16) tpose_body(wk, 512, out, 2048, blockIdx.x, blockIdx.y);
    } else {
        if (blockIdx.x < 16) tpose_body(wv, 512, out, 2560, blockIdx.x, blockIdx.y);
    }
}

__global__ void vtpose() {
    __shared__ float t[32][33];
    int tx = threadIdx.x, ty = threadIdx.y;
    int kvh = blockIdx.z;
    int dim0 = blockIdx.x * 32;
    int seq0 = blockIdx.y * 32;
#pragma unroll
    for (int i = 0; i < 32; i += 8)
        t[ty + i][tx] = g_QKV[(size_t)(seq0 + ty + i) * DQKV_ + 2560 + kvh * HD_ + dim0 + tx];
    __syncthreads();
#pragma unroll
    for (int i = 0; i < 32; i += 8)
        g_Vth[(size_t)kvh * HD_ * SEQ_ + (size_t)(dim0 + ty + i) * SEQ_ + seq0 + tx] =
            __float2half_rn(t[tx][ty + i]);
}

// ---------------------------------------------------------------------------
// Fused RMSNorm + RoPE. Q pass: fp32 in place. K pass: fp16 out to g_Kh.
// ---------------------------------------------------------------------------
__global__ void norm_rope(float* __restrict__ X, const float* __restrict__ w,
                          const float* __restrict__ cosp, const float* __restrict__ sinp,
                          int nheads, int rowdim, __half* __restrict__ hout) {
    int gwarp = (blockIdx.x * blockDim.x + threadIdx.x) >> 5;
    int lane = threadIdx.x & 31;
    int s = gwarp / nheads;
    int h = gwarp % nheads;
    if (s >= SEQ_) return;

    float* p = X + (size_t)s * rowdim + h * HD_;
    float x0 = p[lane];
    float x1 = p[lane + 32];

    float ss = x0 * x0 + x1 * x1;
#pragma unroll
    for (int off = 16; off; off >>= 1) ss += __shfl_xor_sync(0xFFFFFFFFu, ss, off);
    float r = rsqrtf(ss * (1.f / 64.f) + 1e-6f);

    x0 = x0 * r * w[lane];
    x1 = x1 * r * w[lane + 32];

    float c0 = cosp[s * HD_ + lane],      s0 = sinp[s * HD_ + lane];
    float c1 = cosp[s * HD_ + lane + 32], s1 = sinp[s * HD_ + lane + 32];

    float y0 = x0 * c0 - x1 * s0;
    float y1 = x1 * c1 + x0 * s1;
    if (hout) {
        __half* q = hout + (size_t)s * 512 + h * HD_;
        q[lane]      = __float2half_rn(y0);
        q[lane + 32] = __float2half_rn(y1);
    } else {
        p[lane]      = y0;
        p[lane + 32] = y1;
    }
}

// ---------------------------------------------------------------------------
// fp16 mma.sync GEMM (R13 pipeline, 8-warp split): C = A[M,2048] @ Bt[N,2048]^T.
// CTA tile 64x128, BK=32, 8 warps (2x4, warp tile 32x32), 256 threads,
// 4-stage cp.async, 3 CTAs/SM. Row stride 20 words -> conflict-free LDS.
// ---------------------------------------------------------------------------
#define NCHG_   (GK_ / 32)      // 64
#define GW_     20              // words per smem row (32 halves + pad)
#define AROWS_  64
#define SROWS_  192             // 64 A rows + 128 B rows
#define SSTG_W  (SROWS_ * GW_)  // 3840 words per stage
#define GNSTG_  4

__global__ __launch_bounds__(256, 3) void gemm_f16(
    const __half* __restrict__ A, const __half* __restrict__ Bt,
    float* __restrict__ C, int ldc)
{
    extern __shared__ uint32_t smw[];
    const int tid = threadIdx.x;
    const int w = tid >> 5, lane = tid & 31;
    const int bm = blockIdx.y * 64, bn = blockIdx.x * 128;
    const int warp_m = (w & 1) * 32, warp_n = (w >> 1) * 32;
    const int tr = lane >> 2, tc = lane & 3;

    float acc[2][4][4];
#pragma unroll
    for (int i = 0; i < 2; i++)
#pragma unroll
        for (int j = 0; j < 4; j++)
#pragma unroll
            for (int r = 0; r < 4; r++) acc[i][j][r] = 0.f;

    const __half* Ag = A + (size_t)bm * GK_;
    const __half* Bg = Bt + (size_t)bn * GK_;
    uint32_t sbase = smem_u32(smw);

    // cp.async mapping (256 threads): A 64 rows = 256 chunks (1/thread),
    // B 128 rows = 512 chunks (2/thread). chunk = 16 B.
    const int arow = tid >> 2, aq = tid & 3;

    auto issue = [&](int c) {
        uint32_t sA = sbase + (uint32_t)(c & 3) * SSTG_W * 4;
        uint32_t sB = sA + AROWS_ * GW_ * 4;
        const int k0 = c * 32;
        cpasync16(sA + (uint32_t)(arow * GW_ + aq * 4) * 4,
                  Ag + (size_t)arow * GK_ + k0 + aq * 8);
#pragma unroll
        for (int i = 0; i < 2; i++) {
            int ci = tid + i * 256;
            int row = ci >> 2, q = ci & 3;
            cpasync16(sB + (uint32_t)(row * GW_ + q * 4) * 4,
                      Bg + (size_t)row * GK_ + k0 + q * 8);
        }
        CP_COMMIT();
    };

    issue(0); issue(1); issue(2);

    for (int c = 0; c < NCHG_; c++) {
        const int rem = NCHG_ - 1 - c;
        if (rem >= 2) CP_WAIT(2);
        else if (rem == 1) CP_WAIT(1);
        else CP_WAIT(0);
        __syncthreads();
        if (c + 3 < NCHG_) issue(c + 3);    // stage (c+3)&3 == (c-1)&3: freed by barrier

        const uint32_t* As = smw + (c & 3) * SSTG_W;
        const uint32_t* Bs = As + AROWS_ * GW_;

#pragma unroll
        for (int kk = 0; kk < 2; kk++) {
            const int kb = kk * 8;
            uint32_t a[2][4], b[4][2];
#pragma unroll
            for (int mt = 0; mt < 2; mt++) {
                const uint32_t* ap = As + (warp_m + mt * 16 + tr) * GW_ + kb + tc;
                a[mt][0] = ap[0];
                a[mt][1] = ap[8 * GW_];
                a[mt][2] = ap[4];
                a[mt][3] = ap[8 * GW_ + 4];
            }
#pragma unroll
            for (int nt = 0; nt < 4; nt++) {
                const uint32_t* bp = Bs + (warp_n + nt * 8 + tr) * GW_ + kb + tc;
                b[nt][0] = bp[0];
                b[nt][1] = bp[4];
            }
#pragma unroll
            for (int mt = 0; mt < 2; mt++)
#pragma unroll
                for (int nt = 0; nt < 4; nt++)
                    mma_f16(acc[mt][nt], a[mt], b[nt]);
        }
    }

#pragma unroll
    for (int mt = 0; mt < 2; mt++)
#pragma unroll
        for (int nt = 0; nt < 4; nt++) {
            int row = bm + warp_m + mt * 16 + tr;
            int col = bn + warp_n + nt * 8 + 2 * tc;
            *(float2*)(C + (size_t)row * ldc + col) =
                make_float2(acc[mt][nt][0], acc[mt][nt][1]);
            *(float2*)(C + (size_t)(row + 8) * ldc + col) =
                make_float2(acc[mt][nt][2], acc[mt][nt][3]);
        }
}

// ---------------------------------------------------------------------------
// fp16 tensor-core causal GQA flash attention (R13 version, scalar LDS frags).
// Heavy q-blocks scheduled first via reversed blockIdx.x.
// ---------------------------------------------------------------------------
#define QS_ST   68
#define KW_     36
#define VW_     20
#define KS_OFFW (128 * QS_ST)
#define VS_OFFW (KS_OFFW + 2 * 32 * KW_)
#define FA_SMW  (VS_OFFW + 2 * 64 * VW_)    // 13568 words = 54272 B

__global__ __launch_bounds__(256, 2) void flash_f16() {
    extern __shared__ uint32_t smw[];
    float* Qs = (float*)smw;
    const int tid = threadIdx.x;
    const int w = tid >> 5, lane = tid & 31;
    const int tr = lane >> 2, tc = lane & 3;
    const int h = blockIdx.y;
    const int q0 = (gridDim.x - 1 - blockIdx.x) * 128;   // heavy blocks first
    const int kvh = h >> 2;
    const uint32_t sb = smem_u32(smw);

    const __half* Kg = g_Kh + kvh * HD_;
    const __half* Vg = g_Vth + (size_t)kvh * HD_ * SEQ_;

    {
        int kr = tid >> 3, kq = tid & 7;
        cpasync16(sb + (KS_OFFW + kr * KW_ + kq * 4) * 4,
                  Kg + (size_t)kr * 512 + kq * 8);
        int vr = tid >> 2, vq = tid & 3;
        cpasync16(sb + (VS_OFFW + vr * VW_ + vq * 4) * 4,
                  Vg + (size_t)vr * SEQ_ + vq * 8);
        CP_COMMIT();
    }

    {
        const float* Qgp = g_QKV + (size_t)q0 * DQKV_ + h * HD_;
#pragma unroll
        for (int i = 0; i < 8; i++) {
            int idx = tid + i * 256;
            int row = idx >> 4, c4 = idx & 15;
            *(float4*)&Qs[row * QS_ST + c4 * 4] =
                *(const float4*)(Qgp + (size_t)row * DQKV_ + c4 * 4);
        }
    }
    __syncthreads();

    uint32_t q[4][4];
    {
        const float scale = 0.125f;
        const float* q0p = Qs + (w * 16 + tr) * QS_ST;
        const float* q1p = q0p + 8 * QS_ST;
#pragma unroll
        for (int kk = 0; kk < 4; kk++) {
            int c = 16 * kk + 2 * tc;
            q[kk][0] = packh2(q0p[c] * scale, q0p[c + 1] * scale);
            q[kk][1] = packh2(q1p[c] * scale, q1p[c + 1] * scale);
            q[kk][2] = packh2(q0p[c + 8] * scale, q0p[c + 9] * scale);
            q[kk][3] = packh2(q1p[c + 8] * scale, q1p[c + 9] * scale);
        }
    }

    float o[8][4];
#pragma unroll
    for (int nf = 0; nf < 8; nf++)
#pragma unroll
        for (int r = 0; r < 4; r++) o[nf][r] = 0.f;
    float m0 = -1e30f, m1 = -1e30f, l0 = 0.f, l1 = 0.f;

    const int ntiles = (q0 + 128) / 32;

    for (int t = 0; t < ntiles; t++) {
        const int k0 = t * 32;
        if (t + 1 < ntiles) {
            const int kn = (t + 1) * 32;
            const int buf = (t + 1) & 1;
            int kr = tid >> 3, kq = tid & 7;
            cpasync16(sb + (KS_OFFW + (buf * 32 + kr) * KW_ + kq * 4) * 4,
                      Kg + (size_t)(kn + kr) * 512 + kq * 8);
            int vr = tid >> 2, vq = tid & 3;
            cpasync16(sb + (VS_OFFW + (buf * 64 + vr) * VW_ + vq * 4) * 4,
                      Vg + (size_t)vr * SEQ_ + kn + vq * 8);
            CP_COMMIT();
            CP_WAIT(1);
        } else {
            CP_WAIT(0);
        }
        __syncthreads();

        if (k0 <= q0 + w * 16 + 15) {
            const uint32_t* Kt = smw + KS_OFFW + (t & 1) * 32 * KW_;
            const uint32_t* Vt = smw + VS_OFFW + (t & 1) * 64 * VW_;

            float s[4][4];
#pragma unroll
            for (int nf = 0; nf < 4; nf++) {
                s[nf][0] = s[nf][1] = s[nf][2] = s[nf][3] = 0.f;
                const uint32_t* bp = Kt + (nf * 8 + tr) * KW_ + tc;
#pragma unroll
                for (int kk = 0; kk < 4; kk++) {
                    uint32_t b[2] = { bp[kk * 8], bp[kk * 8 + 4] };
                    mma_f16(s[nf], q[kk], b);
                }
            }

            if (k0 + 31 > q0 + w * 16) {
                const int r0 = q0 + w * 16 + tr, r1 = r0 + 8;
                const int cb = k0 + 2 * tc;
#pragma unroll
                for (int nf = 0; nf < 4; nf++) {
                    int c0 = cb + nf * 8, c1 = c0 + 1;
                    if (c0 > r0) s[nf][0] = -1e30f;
                    if (c1 > r0) s[nf][1] = -1e30f;
                    if (c0 > r1) s[nf][2] = -1e30f;
                    if (c1 > r1) s[nf][3] = -1e30f;
                }
            }

            float t0 = fmaxf(fmaxf(s[0][0], s[0][1]), fmaxf(s[1][0], s[1][1]));
            t0 = fmaxf(t0, fmaxf(fmaxf(s[2][0], s[2][1]), fmaxf(s[3][0], s[3][1])));
            float t1 = fmaxf(fmaxf(s[0][2], s[0][3]), fmaxf(s[1][2], s[1][3]));
            t1 = fmaxf(t1, fmaxf(fmaxf(s[2][2], s[2][3]), fmaxf(s[3][2], s[3][3])));
            t0 = fmaxf(t0, __shfl_xor_sync(0xFFFFFFFFu, t0, 1));
            t0 = fmaxf(t0, __shfl_xor_sync(0xFFFFFFFFu, t0, 2));
            t1 = fmaxf(t1, __shfl_xor_sync(0xFFFFFFFFu, t1, 1));
            t1 = fmaxf(t1, __shfl_xor_sync(0xFFFFFFFFu, t1, 2));
            const float mt0 = fmaxf(m0, t0), mt1 = fmaxf(m1, t1);
            const float corr0 = __expf(m0 - mt0), corr1 = __expf(m1 - mt1);
            m0 = mt0; m1 = mt1;

            float pv[4][4];
            float sum0 = 0.f, sum1 = 0.f;
#pragma unroll
            for (int nf = 0; nf < 4; nf++) {
                pv[nf][0] = __expf(s[nf][0] - mt0);
                pv[nf][1] = __expf(s[nf][1] - mt0);
                pv[nf][2] = __expf(s[nf][2] - mt1);
                pv[nf][3] = __expf(s[nf][3] - mt1);
                sum0 += pv[nf][0] + pv[nf][1];
                sum1 += pv[nf][2] + pv[nf][3];
            }
            sum0 += __shfl_xor_sync(0xFFFFFFFFu, sum0, 1);
            sum0 += __shfl_xor_sync(0xFFFFFFFFu, sum0, 2);
            sum1 += __shfl_xor_sync(0xFFFFFFFFu, sum1, 1);
            sum1 += __shfl_xor_sync(0xFFFFFFFFu, sum1, 2);
            l0 = l0 * corr0 + sum0;
            l1 = l1 * corr1 + sum1;

#pragma unroll
            for (int nf = 0; nf < 8; nf++) {
                o[nf][0] *= corr0; o[nf][1] *= corr0;
                o[nf][2] *= corr1; o[nf][3] *= corr1;
            }

#pragma unroll
            for (int kkp = 0; kkp < 2; kkp++) {
                uint32_t a[4] = {
                    packh2(pv[2 * kkp][0],     pv[2 * kkp][1]),
                    packh2(pv[2 * kkp][2],     pv[2 * kkp][3]),
                    packh2(pv[2 * kkp + 1][0], pv[2 * kkp + 1][1]),
                    packh2(pv[2 * kkp + 1][2], pv[2 * kkp + 1][3])
                };
#pragma unroll
                for (int nt = 0; nt < 8; nt++) {
                    const uint32_t* vp = Vt + (nt * 8 + tr) * VW_ + kkp * 8 + tc;
                    uint32_t b[2] = { vp[0], vp[4] };
                    mma_f16(o[nt], a, b);
                }
            }
        }
        __syncthreads();
    }

    const float inv0 = 1.f / l0, inv1 = 1.f / l1;
    const int r0 = q0 + w * 16 + tr;
    uint32_t* Og = (uint32_t*)(g_Ah + (size_t)r0 * DOUT_ + h * HD_ + 2 * tc);
    uint32_t* Og8 = (uint32_t*)(g_Ah + (size_t)(r0 + 8) * DOUT_ + h * HD_ + 2 * tc);
#pragma unroll
    for (int nf = 0; nf < 8; nf++) {
        Og[nf * 4]  = packh2(o[nf][0] * inv0, o[nf][1] * inv0);
        Og8[nf * 4] = packh2(o[nf][2] * inv1, o[nf][3] * inv1);
    }
}

// ---------------------------------------------------------------------------
extern "C" void kernel_launch(void* const* d_in, const int* in_sizes, int n_in,
                              void* d_out, int out_size) {
    const float* x    = (const float*)d_in[0];
    const float* cosp = (const float*)d_in[1];
    const float* sinp = (const float*)d_in[2];
    const float* wq   = (const float*)d_in[3];
    const float* wk   = (const float*)d_in[4];
    const float* wv   = (const float*)d_in[5];
    const float* wo   = (const float*)d_in[6];
    const float* qw   = (const float*)d_in[7];
    const float* kw   = (const float*)d_in[8];
    float* out = (float*)d_out;

    float *QKV;
    __half *xh, *wth, *woth, *Kh, *Ah;
    cudaGetSymbolAddress((void**)&xh,   g_xh);
    cudaGetSymbolAddress((void**)&wth,  g_wth);
    cudaGetSymbolAddress((void**)&woth, g_woth);
    cudaGetSymbolAddress((void**)&QKV,  g_QKV);
    cudaGetSymbolAddress((void**)&Kh,   g_Kh);
    cudaGetSymbolAddress((void**)&Ah,   g_Ah);

    const int gsmem = GNSTG_ * SSTG_W * 4;    // 61440 B (4 stages)
    cudaFuncSetAttribute(gemm_f16, cudaFuncAttributeMaxDynamicSharedMemorySize, gsmem);
    const int fsmem = FA_SMW * 4;             // 54272 B
    cudaFuncSetAttribute(flash_f16, cudaFuncAttributeMaxDynamicSharedMemorySize, fsmem);

    // Prep: x -> fp16; weights transpose -> fp16
    cvt_h<<<(SEQ_ * DIN_ / 2 + 255) / 256, 256>>>(x, xh, SEQ_ * DIN_ / 2);
    tposer3<<<dim3(64, DIN_ / 32, 3), dim3(32, 8)>>>(wq, wk, wv, wth);
    tposer<<<dim3(2048 / 32, DOUT_ / 32), dim3(32, 8)>>>(wo, 2048, woth, 0);

    // Fused QKV projection (fp16 tensor cores, fp32 out), 64x128 tiles
    gemm_f16<<<dim3(DQKV_ / 128, SEQ_ / 64), 256, gsmem>>>(xh, wth, QKV, DQKV_);

    // RMSNorm + RoPE: Q in place fp32; K -> fp16 g_Kh. V -> transposed fp16.
    norm_rope<<<(SEQ_ * NH_ * 32) / 256, 256>>>(QKV, qw, cosp, sinp, NH_, DQKV_, (half*)0);
    norm_rope<<<(SEQ_ * NKV_ * 32) / 256, 256>>>(QKV + 2048, kw, cosp, sinp, NKV_, DQKV_, Kh);
    vtpose<<<dim3(HD_ / 32, SEQ_ / 32, NKV_), dim3(32, 8)>>>();

    // Tensor-core causal GQA attention (fp16), writes fp16 g_Ah
    flash_f16<<<dim3(SEQ_ / 128, NH_), 256, fsmem>>>();

    // Output projection (fp16 tensor cores, fp32 out), 64x128 tiles
    gemm_f16<<<dim3(DIN_ / 128, SEQ_ / 64), 256, gsmem>>>(Ah, woth, out, DIN_);
}

// round 17
// speedup vs baseline: 1.3833x; 1.0978x over previous
#include <cuda_runtime.h>
#include <cuda_fp16.h>
#include <cstdint>
#include <math.h>

#define SEQ_    2048
#define DIN_    2048
#define NH_     32
#define NKV_    8
#define HD_     64
#define DQKV_   3072            // Q(2048) | K(512) | V(512) fused columns
#define DOUT_   2048
#define GK_     2048

// ---------------------------------------------------------------------------
// Scratch (__device__ globals; allocation-free rule)
// ---------------------------------------------------------------------------
__device__ __half g_xh[SEQ_ * DIN_];
__device__ __half g_wth[DQKV_ * DIN_];
__device__ __half g_woth[DIN_ * DOUT_];
__device__ float  g_QKV[SEQ_ * DQKV_];
__device__ __half g_Kh[SEQ_ * 512];
__device__ __half g_Vth[NKV_ * HD_ * SEQ_];
__device__ __half g_Ah[SEQ_ * DOUT_];

// Host-side aux streams/events (created once at program load; host objects)
struct Aux {
    cudaStream_t s1, s2;
    cudaEvent_t e0, e1, e2;
    Aux() {
        cudaStreamCreateWithFlags(&s1, cudaStreamNonBlocking);
        cudaStreamCreateWithFlags(&s2, cudaStreamNonBlocking);
        cudaEventCreateWithFlags(&e0, cudaEventDisableTiming);
        cudaEventCreateWithFlags(&e1, cudaEventDisableTiming);
        cudaEventCreateWithFlags(&e2, cudaEventDisableTiming);
    }
};
static Aux g_aux;

// ---------------------------------------------------------------------------
// Helpers (baseline PTX only)
// ---------------------------------------------------------------------------
__device__ __forceinline__ uint32_t smem_u32(const void* p) {
    uint32_t a;
    asm("{ .reg .u64 t; cvta.to.shared.u64 t, %1; cvt.u32.u64 %0, t; }" : "=r"(a) : "l"(p));
    return a;
}
__device__ __forceinline__ void cpasync16(uint32_t dst, const void* src) {
    asm volatile("cp.async.cg.shared.global [%0], [%1], 16;" :: "r"(dst), "l"(src));
}
#define CP_COMMIT()  asm volatile("cp.async.commit_group;" ::: "memory")
#define CP_WAIT(n)   asm volatile("cp.async.wait_group %0;" :: "n"(n) : "memory")

__device__ __forceinline__ void mma_f16(float* d, const uint32_t* a, const uint32_t* b) {
    asm volatile(
        "mma.sync.aligned.m16n8k16.row.col.f32.f16.f16.f32 "
        "{%0,%1,%2,%3}, {%4,%5,%6,%7}, {%8,%9}, {%0,%1,%2,%3};"
        : "+f"(d[0]), "+f"(d[1]), "+f"(d[2]), "+f"(d[3])
        : "r"(a[0]), "r"(a[1]), "r"(a[2]), "r"(a[3]), "r"(b[0]), "r"(b[1]));
}
__device__ __forceinline__ uint32_t packh2(float x, float y) {
    __half2 h = __floats2half2_rn(x, y);
    return *(uint32_t*)&h;
}

// ---------------------------------------------------------------------------
// Prep kernels
// ---------------------------------------------------------------------------
__global__ void cvt_h(const float* __restrict__ src, __half* __restrict__ dst, int n2) {
    int i = blockIdx.x * blockDim.x + threadIdx.x;
    if (i >= n2) return;
    float2 v = ((const float2*)src)[i];
    ((uint32_t*)dst)[i] = packh2(v.x, v.y);
}

__device__ __forceinline__ void tpose_body(const float* __restrict__ W, int ncols,
                                           __half* __restrict__ out, int row_off,
                                           int bx, int by) {
    __shared__ float t[32][33];
    int tx = threadIdx.x, ty = threadIdx.y;
    int x = bx * 32 + tx;
    int y = by * 32 + ty;
#pragma unroll
    for (int i = 0; i < 32; i += 8)
        t[ty + i][tx] = W[(size_t)(y + i) * ncols + x];
    __syncthreads();
    int n = bx * 32 + ty;
    int k = by * 32 + tx;
#pragma unroll
    for (int i = 0; i < 32; i += 8)
        out[(size_t)(row_off + n + i) * GK_ + k] = __float2half_rn(t[tx][ty + i]);
}

__global__ void tposer(const float* __restrict__ W, int ncols,
                       __half* __restrict__ out, int row_off) {
    tpose_body(W, ncols, out, row_off, blockIdx.x, blockIdx.y);
}

__global__ void tposer3(const float* __restrict__ wq, const float* __restrict__ wk,
                        const float* __restrict__ wv, __half* __restrict__ out) {
    int z = blockIdx.z;
    if (z == 0) {
        tpose_body(wq, 2048, out, 0, blockIdx.x, blockIdx.y);
    } else if (z == 1) {
        if (blockIdx.x < 16) tpose_body(wk, 512, out, 2048, blockIdx.x, blockIdx.y);
    } else {
        if (blockIdx.x < 16) tpose_body(wv, 512, out, 2560, blockIdx.x, blockIdx.y);
    }
}

__global__ void vtpose() {
    __shared__ float t[32][33];
    int tx = threadIdx.x, ty = threadIdx.y;
    int kvh = blockIdx.z;
    int dim0 = blockIdx.x * 32;
    int seq0 = blockIdx.y * 32;
#pragma unroll
    for (int i = 0; i < 32; i += 8)
        t[ty + i][tx] = g_QKV[(size_t)(seq0 + ty + i) * DQKV_ + 2560 + kvh * HD_ + dim0 + tx];
    __syncthreads();
#pragma unroll
    for (int i = 0; i < 32; i += 8)
        g_Vth[(size_t)kvh * HD_ * SEQ_ + (size_t)(dim0 + ty + i) * SEQ_ + seq0 + tx] =
            __float2half_rn(t[tx][ty + i]);
}

// ---------------------------------------------------------------------------
// Fused RMSNorm + RoPE for Q (32 heads, fp32 in place) and K (8 heads ->
// fp16 g_Kh) in ONE launch: 40 virtual heads per token.
// ---------------------------------------------------------------------------
__global__ void norm_rope_all(const float* __restrict__ cosp, const float* __restrict__ sinp,
                              const float* __restrict__ qw, const float* __restrict__ kw) {
    int gwarp = (blockIdx.x * blockDim.x + threadIdx.x) >> 5;
    int lane = threadIdx.x & 31;
    int s = gwarp / 40;
    int h = gwarp % 40;
    if (s >= SEQ_) return;

    const bool isQ = (h < 32);
    const float* w = isQ ? qw : kw;
    float* p = g_QKV + (size_t)s * DQKV_ + (isQ ? h * HD_ : 2048 + (h - 32) * HD_);

    float x0 = p[lane];
    float x1 = p[lane + 32];

    float ss = x0 * x0 + x1 * x1;
#pragma unroll
    for (int off = 16; off; off >>= 1) ss += __shfl_xor_sync(0xFFFFFFFFu, ss, off);
    float r = rsqrtf(ss * (1.f / 64.f) + 1e-6f);

    x0 = x0 * r * w[lane];
    x1 = x1 * r * w[lane + 32];

    float c0 = cosp[s * HD_ + lane],      s0 = sinp[s * HD_ + lane];
    float c1 = cosp[s * HD_ + lane + 32], s1 = sinp[s * HD_ + lane + 32];

    float y0 = x0 * c0 - x1 * s0;
    float y1 = x1 * c1 + x0 * s1;
    if (isQ) {
        p[lane]      = y0;
        p[lane + 32] = y1;
    } else {
        __half* q = g_Kh + (size_t)s * 512 + (h - 32) * HD_;
        q[lane]      = __float2half_rn(y0);
        q[lane + 32] = __float2half_rn(y1);
    }
}

// ---------------------------------------------------------------------------
// fp16 mma.sync GEMM — EXACT R13 config: CTA 64x128, 4 warps (2x2, warp
// tile 32x64), 128 threads, 4-stage cp.async, 3 CTAs/SM, scalar LDS frags.
// ---------------------------------------------------------------------------
#define NCHG_   (GK_ / 32)      // 64
#define GW_     20
#define AROWS_  64
#define SROWS_  192
#define SSTG_W  (SROWS_ * GW_)  // 3840 words
#define GNSTG_  4

__global__ __launch_bounds__(128, 3) void gemm_f16(
    const __half* __restrict__ A, const __half* __restrict__ Bt,
    float* __restrict__ C, int ldc)
{
    extern __shared__ uint32_t smw[];
    const int tid = threadIdx.x;
    const int w = tid >> 5, lane = tid & 31;
    const int bm = blockIdx.y * 64, bn = blockIdx.x * 128;
    const int warp_m = (w & 1) * 32, warp_n = (w >> 1) * 64;
    const int tr = lane >> 2, tc = lane & 3;

    float acc[2][8][4];
#pragma unroll
    for (int i = 0; i < 2; i++)
#pragma unroll
        for (int j = 0; j < 8; j++)
#pragma unroll
            for (int r = 0; r < 4; r++) acc[i][j][r] = 0.f;

    const __half* Ag = A + (size_t)bm * GK_;
    const __half* Bg = Bt + (size_t)bn * GK_;
    const int lrow = tid >> 2;
    const int lq = tid & 3;
    uint32_t sbase = smem_u32(smw);

    auto issue = [&](int c) {
        uint32_t sA = sbase + (uint32_t)(c & 3) * SSTG_W * 4;
        uint32_t sB = sA + AROWS_ * GW_ * 4;
        const int k0 = c * 32;
#pragma unroll
        for (int i = 0; i < 2; i++) {
            int row = lrow + i * 32;
            cpasync16(sA + (uint32_t)(row * GW_ + lq * 4) * 4,
                      Ag + (size_t)row * GK_ + k0 + lq * 8);
        }
#pragma unroll
        for (int i = 0; i < 4; i++) {
            int row = lrow + i * 32;
            cpasync16(sB + (uint32_t)(row * GW_ + lq * 4) * 4,
                      Bg + (size_t)row * GK_ + k0 + lq * 8);
        }
        CP_COMMIT();
    };

    issue(0); issue(1); issue(2);

    for (int c = 0; c < NCHG_; c++) {
        const int rem = NCHG_ - 1 - c;
        if (rem >= 2) CP_WAIT(2);
        else if (rem == 1) CP_WAIT(1);
        else CP_WAIT(0);
        __syncthreads();
        if (c + 3 < NCHG_) issue(c + 3);

        const uint32_t* As = smw + (c & 3) * SSTG_W;
        const uint32_t* Bs = As + AROWS_ * GW_;

#pragma unroll
        for (int kk = 0; kk < 2; kk++) {
            const int kb = kk * 8;
            uint32_t a[2][4], b[8][2];
#pragma unroll
            for (int mt = 0; mt < 2; mt++) {
                const uint32_t* ap = As + (warp_m + mt * 16 + tr) * GW_ + kb + tc;
                a[mt][0] = ap[0];
                a[mt][1] = ap[8 * GW_];
                a[mt][2] = ap[4];
                a[mt][3] = ap[8 * GW_ + 4];
            }
#pragma unroll
            for (int nt = 0; nt < 8; nt++) {
                const uint32_t* bp = Bs + (warp_n + nt * 8 + tr) * GW_ + kb + tc;
                b[nt][0] = bp[0];
                b[nt][1] = bp[4];
            }
#pragma unroll
            for (int mt = 0; mt < 2; mt++)
#pragma unroll
                for (int nt = 0; nt < 8; nt++)
                    mma_f16(acc[mt][nt], a[mt], b[nt]);
        }
    }

#pragma unroll
    for (int mt = 0; mt < 2; mt++)
#pragma unroll
        for (int nt = 0; nt < 8; nt++) {
            int row = bm + warp_m + mt * 16 + tr;
            int col = bn + warp_n + nt * 8 + 2 * tc;
            *(float2*)(C + (size_t)row * ldc + col) =
                make_float2(acc[mt][nt][0], acc[mt][nt][1]);
            *(float2*)(C + (size_t)(row + 8) * ldc + col) =
                make_float2(acc[mt][nt][2], acc[mt][nt][3]);
        }
}

// ---------------------------------------------------------------------------
// fp16 flash attention — EXACT R13 kernel + reversed q-block scheduling.
// ---------------------------------------------------------------------------
#define QS_ST   68
#define KW_     36
#define VW_     20
#define KS_OFFW (128 * QS_ST)
#define VS_OFFW (KS_OFFW + 2 * 32 * KW_)
#define FA_SMW  (VS_OFFW + 2 * 64 * VW_)    // 13568 words = 54272 B

__global__ __launch_bounds__(256, 2) void flash_f16() {
    extern __shared__ uint32_t smw[];
    float* Qs = (float*)smw;
    const int tid = threadIdx.x;
    const int w = tid >> 5, lane = tid & 31;
    const int tr = lane >> 2, tc = lane & 3;
    const int h = blockIdx.y;
    const int q0 = (gridDim.x - 1 - blockIdx.x) * 128;   // heavy blocks first
    const int kvh = h >> 2;
    const uint32_t sb = smem_u32(smw);

    const __half* Kg = g_Kh + kvh * HD_;
    const __half* Vg = g_Vth + (size_t)kvh * HD_ * SEQ_;

    {
        int kr = tid >> 3, kq = tid & 7;
        cpasync16(sb + (KS_OFFW + kr * KW_ + kq * 4) * 4,
                  Kg + (size_t)kr * 512 + kq * 8);
        int vr = tid >> 2, vq = tid & 3;
        cpasync16(sb + (VS_OFFW + vr * VW_ + vq * 4) * 4,
                  Vg + (size_t)vr * SEQ_ + vq * 8);
        CP_COMMIT();
    }

    {
        const float* Qgp = g_QKV + (size_t)q0 * DQKV_ + h * HD_;
#pragma unroll
        for (int i = 0; i < 8; i++) {
            int idx = tid + i * 256;
            int row = idx >> 4, c4 = idx & 15;
            *(float4*)&Qs[row * QS_ST + c4 * 4] =
                *(const float4*)(Qgp + (size_t)row * DQKV_ + c4 * 4);
        }
    }
    __syncthreads();

    uint32_t q[4][4];
    {
        const float scale = 0.125f;
        const float* q0p = Qs + (w * 16 + tr) * QS_ST;
        const float* q1p = q0p + 8 * QS_ST;
#pragma unroll
        for (int kk = 0; kk < 4; kk++) {
            int c = 16 * kk + 2 * tc;
            q[kk][0] = packh2(q0p[c] * scale, q0p[c + 1] * scale);
            q[kk][1] = packh2(q1p[c] * scale, q1p[c + 1] * scale);
            q[kk][2] = packh2(q0p[c + 8] * scale, q0p[c + 9] * scale);
            q[kk][3] = packh2(q1p[c + 8] * scale, q1p[c + 9] * scale);
        }
    }

    float o[8][4];
#pragma unroll
    for (int nf = 0; nf < 8; nf++)
#pragma unroll
        for (int r = 0; r < 4; r++) o[nf][r] = 0.f;
    float m0 = -1e30f, m1 = -1e30f, l0 = 0.f, l1 = 0.f;

    const int ntiles = (q0 + 128) / 32;

    for (int t = 0; t < ntiles; t++) {
        const int k0 = t * 32;
        if (t + 1 < ntiles) {
            const int kn = (t + 1) * 32;
            const int buf = (t + 1) & 1;
            int kr = tid >> 3, kq = tid & 7;
            cpasync16(sb + (KS_OFFW + (buf * 32 + kr) * KW_ + kq * 4) * 4,
                      Kg + (size_t)(kn + kr) * 512 + kq * 8);
            int vr = tid >> 2, vq = tid & 3;
            cpasync16(sb + (VS_OFFW + (buf * 64 + vr) * VW_ + vq * 4) * 4,
                      Vg + (size_t)vr * SEQ_ + kn + vq * 8);
            CP_COMMIT();
            CP_WAIT(1);
        } else {
            CP_WAIT(0);
        }
        __syncthreads();

        if (k0 <= q0 + w * 16 + 15) {
            const uint32_t* Kt = smw + KS_OFFW + (t & 1) * 32 * KW_;
            const uint32_t* Vt = smw + VS_OFFW + (t & 1) * 64 * VW_;

            float s[4][4];
#pragma unroll
            for (int nf = 0; nf < 4; nf++) {
                s[nf][0] = s[nf][1] = s[nf][2] = s[nf][3] = 0.f;
                const uint32_t* bp = Kt + (nf * 8 + tr) * KW_ + tc;
#pragma unroll
                for (int kk = 0; kk < 4; kk++) {
                    uint32_t b[2] = { bp[kk * 8], bp[kk * 8 + 4] };
                    mma_f16(s[nf], q[kk], b);
                }
            }

            if (k0 + 31 > q0 + w * 16) {
                const int r0 = q0 + w * 16 + tr, r1 = r0 + 8;
                const int cb = k0 + 2 * tc;
#pragma unroll
                for (int nf = 0; nf < 4; nf++) {
                    int c0 = cb + nf * 8, c1 = c0 + 1;
                    if (c0 > r0) s[nf][0] = -1e30f;
                    if (c1 > r0) s[nf][1] = -1e30f;
                    if (c0 > r1) s[nf][2] = -1e30f;
                    if (c1 > r1) s[nf][3] = -1e30f;
                }
            }

            float t0 = fmaxf(fmaxf(s[0][0], s[0][1]), fmaxf(s[1][0], s[1][1]));
            t0 = fmaxf(t0, fmaxf(fmaxf(s[2][0], s[2][1]), fmaxf(s[3][0], s[3][1])));
            float t1 = fmaxf(fmaxf(s[0][2], s[0][3]), fmaxf(s[1][2], s[1][3]));
            t1 = fmaxf(t1, fmaxf(fmaxf(s[2][2], s[2][3]), fmaxf(s[3][2], s[3][3])));
            t0 = fmaxf(t0, __shfl_xor_sync(0xFFFFFFFFu, t0, 1));
            t0 = fmaxf(t0, __shfl_xor_sync(0xFFFFFFFFu, t0, 2));
            t1 = fmaxf(t1, __shfl_xor_sync(0xFFFFFFFFu, t1, 1));
            t1 = fmaxf(t1, __shfl_xor_sync(0xFFFFFFFFu, t1, 2));
            const float mt0 = fmaxf(m0, t0), mt1 = fmaxf(m1, t1);
            const float corr0 = __expf(m0 - mt0), corr1 = __expf(m1 - mt1);
            m0 = mt0; m1 = mt1;

            float pv[4][4];
            float sum0 = 0.f, sum1 = 0.f;
#pragma unroll
            for (int nf = 0; nf < 4; nf++) {
                pv[nf][0] = __expf(s[nf][0] - mt0);
                pv[nf][1] = __expf(s[nf][1] - mt0);
                pv[nf][2] = __expf(s[nf][2] - mt1);
                pv[nf][3] = __expf(s[nf][3] - mt1);
                sum0 += pv[nf][0] + pv[nf][1];
                sum1 += pv[nf][2] + pv[nf][3];
            }
            sum0 += __shfl_xor_sync(0xFFFFFFFFu, sum0, 1);
            sum0 += __shfl_xor_sync(0xFFFFFFFFu, sum0, 2);
            sum1 += __shfl_xor_sync(0xFFFFFFFFu, sum1, 1);
            sum1 += __shfl_xor_sync(0xFFFFFFFFu, sum1, 2);
            l0 = l0 * corr0 + sum0;
            l1 = l1 * corr1 + sum1;

#pragma unroll
            for (int nf = 0; nf < 8; nf++) {
                o[nf][0] *= corr0; o[nf][1] *= corr0;
                o[nf][2] *= corr1; o[nf][3] *= corr1;
            }

#pragma unroll
            for (int kkp = 0; kkp < 2; kkp++) {
                uint32_t a[4] = {
                    packh2(pv[2 * kkp][0],     pv[2 * kkp][1]),
                    packh2(pv[2 * kkp][2],     pv[2 * kkp][3]),
                    packh2(pv[2 * kkp + 1][0], pv[2 * kkp + 1][1]),
                    packh2(pv[2 * kkp + 1][2], pv[2 * kkp + 1][3])
                };
#pragma unroll
                for (int nt = 0; nt < 8; nt++) {
                    const uint32_t* vp = Vt + (nt * 8 + tr) * VW_ + kkp * 8 + tc;
                    uint32_t b[2] = { vp[0], vp[4] };
                    mma_f16(o[nt], a, b);
                }
            }
        }
        __syncthreads();
    }

    const float inv0 = 1.f / l0, inv1 = 1.f / l1;
    const int r0 = q0 + w * 16 + tr;
    uint32_t* Og = (uint32_t*)(g_Ah + (size_t)r0 * DOUT_ + h * HD_ + 2 * tc);
    uint32_t* Og8 = (uint32_t*)(g_Ah + (size_t)(r0 + 8) * DOUT_ + h * HD_ + 2 * tc);
#pragma unroll
    for (int nf = 0; nf < 8; nf++) {
        Og[nf * 4]  = packh2(o[nf][0] * inv0, o[nf][1] * inv0);
        Og8[nf * 4] = packh2(o[nf][2] * inv1, o[nf][3] * inv1);
    }
}

// ---------------------------------------------------------------------------
extern "C" void kernel_launch(void* const* d_in, const int* in_sizes, int n_in,
                              void* d_out, int out_size) {
    const float* x    = (const float*)d_in[0];
    const float* cosp = (const float*)d_in[1];
    const float* sinp = (const float*)d_in[2];
    const float* wq   = (const float*)d_in[3];
    const float* wk   = (const float*)d_in[4];
    const float* wv   = (const float*)d_in[5];
    const float* wo   = (const float*)d_in[6];
    const float* qw   = (const float*)d_in[7];
    const float* kw   = (const float*)d_in[8];
    float* out = (float*)d_out;

    float *QKV;
    __half *xh, *wth, *woth, *Kh, *Ah;
    cudaGetSymbolAddress((void**)&xh,   g_xh);
    cudaGetSymbolAddress((void**)&wth,  g_wth);
    cudaGetSymbolAddress((void**)&woth, g_woth);
    cudaGetSymbolAddress((void**)&QKV,  g_QKV);
    cudaGetSymbolAddress((void**)&Kh,   g_Kh);
    cudaGetSymbolAddress((void**)&Ah,   g_Ah);

    const int gsmem = GNSTG_ * SSTG_W * 4;    // 61440 B
    cudaFuncSetAttribute(gemm_f16, cudaFuncAttributeMaxDynamicSharedMemorySize, gsmem);
    const int fsmem = FA_SMW * 4;             // 54272 B
    cudaFuncSetAttribute(flash_f16, cudaFuncAttributeMaxDynamicSharedMemorySize, fsmem);

    // Fork side streams off the capture stream.
    cudaEventRecord(g_aux.e0, 0);

    // s1: wo transpose — independent until the final GEMM.
    cudaStreamWaitEvent(g_aux.s1, g_aux.e0, 0);
    tposer<<<dim3(2048 / 32, DOUT_ / 32), dim3(32, 8), 0, g_aux.s1>>>(wo, 2048, woth, 0);
    cudaEventRecord(g_aux.e1, g_aux.s1);

    // s2: QKV weight transpose — runs parallel with cvt_h.
    cudaStreamWaitEvent(g_aux.s2, g_aux.e0, 0);
    tposer3<<<dim3(64, DIN_ / 32, 3), dim3(32, 8), 0, g_aux.s2>>>(wq, wk, wv, wth);
    cudaEventRecord(g_aux.e2, g_aux.s2);

    // main: x -> fp16
    cvt_h<<<(SEQ_ * DIN_ / 2 + 255) / 256, 256>>>(x, xh, SEQ_ * DIN_ / 2);
    cudaStreamWaitEvent(0, g_aux.e2, 0);       // join tposer3

    // Fused QKV projection
    gemm_f16<<<dim3(DQKV_ / 128, SEQ_ / 64), 128, gsmem>>>(xh, wth, QKV, DQKV_);

    // Fused RMSNorm + RoPE (Q fp32 in place, K fp16 out); V transpose
    norm_rope_all<<<(SEQ_ * 40 * 32) / 256, 256>>>(cosp, sinp, qw, kw);
    vtpose<<<dim3(HD_ / 32, SEQ_ / 32, NKV_), dim3(32, 8)>>>();

    // Tensor-core causal GQA attention
    flash_f16<<<dim3(SEQ_ / 128, NH_), 256, fsmem>>>();

    // Output projection (joins wo transpose)
    cudaStreamWaitEvent(0, g_aux.e1, 0);
    gemm_f16<<<dim3(DIN_ / 128, SEQ_ / 64), 128, gsmem>>>(Ah, woth, out, DIN_);
}